// round 11
// baseline (speedup 1.0000x reference)
#include <cuda_runtime.h>
#include <cuda_fp16.h>
#include <cstdint>

// ---------------- problem constants ----------------
#define B_DIM 16384
#define I_DIM 2048
#define O_DIM 2048
#define K_DIM 12288              // 6 * I_DIM (silu panel + 5 RBF panels)
#define KC 64                    // K elems per pipeline stage (64 fp16 = 128 B row)
#define MT 128                   // CTA tile M
#define NT 128                   // CTA tile N
#define STAGES 3
#define KITERS (K_DIM / KC)      // 192

#define A_STAGE_BYTES (MT * 128)                     // 16384
#define B_STAGE_BYTES (NT * 128)                     // 16384
#define STAGE_BYTES (A_STAGE_BYTES + B_STAGE_BYTES)  // 32768
#define SMEM_BYTES (STAGES * STAGE_BYTES)            // 98304 (x2 CTAs = 192KB/SM)

#define NTILES_X (O_DIM / NT)    // 16
#define NTILES (B_DIM / MT * NTILES_X)   // 2048
#define PERSIST_CTAS 296         // 2 per SM x 148 SMs

// ---------------- scratch (device globals; no runtime allocation) ----------------
__device__ __align__(1024) __half g_A[(size_t)B_DIM * K_DIM];   // ~403 MB
__device__ __align__(1024) __half g_W[(size_t)O_DIM * K_DIM];   // ~50 MB

// ---------------- helpers (compute_103-safe PTX only) ----------------
__device__ __forceinline__ uint32_t smem_u32(const void* p) {
    return (uint32_t)__cvta_generic_to_shared(p);
}

// XOR swizzle: 128B rows, 16B granularity, conflict-free ldmatrix + cp.async
#define SWZ(o) ((o) ^ (((o) >> 3) & 0x70))

__device__ __forceinline__ void cp_async16(uint32_t saddr, const void* gptr) {
    asm volatile("cp.async.cg.shared.global [%0], [%1], 16;"
                 :: "r"(saddr), "l"(gptr) : "memory");
}
__device__ __forceinline__ void cp_commit() {
    asm volatile("cp.async.commit_group;" ::: "memory");
}
__device__ __forceinline__ void cp_wait1() {
    asm volatile("cp.async.wait_group 1;" ::: "memory");
}

__device__ __forceinline__ void st_stream32(void* gptr, uint32_t v) {
    asm volatile("st.global.cs.b32 [%0], %1;" :: "l"(gptr), "r"(v) : "memory");
}

__device__ __forceinline__ void ldmatrix_x4(uint32_t* r, uint32_t addr) {
    asm volatile("ldmatrix.sync.aligned.m8n8.x4.shared.b16 {%0,%1,%2,%3}, [%4];"
                 : "=r"(r[0]), "=r"(r[1]), "=r"(r[2]), "=r"(r[3]) : "r"(addr));
}

__device__ __forceinline__ void mma16816(float* c, const uint32_t* a, const uint32_t* b) {
    asm volatile(
        "mma.sync.aligned.m16n8k16.row.col.f32.f16.f16.f32 "
        "{%0,%1,%2,%3}, {%4,%5,%6,%7}, {%8,%9}, {%0,%1,%2,%3};"
        : "+f"(c[0]), "+f"(c[1]), "+f"(c[2]), "+f"(c[3])
        : "r"(a[0]), "r"(a[1]), "r"(a[2]), "r"(a[3]), "r"(b[0]), "r"(b[1]));
}

// ---------------- pass 1 (merged): expanded activation + combined weight ----------------
#define NA_BLOCKS (B_DIM * I_DIM / 2 / 256)   // 65536
#define NW_BLOCKS (O_DIM * I_DIM / 256)       // 16384

__global__ void build_AW(const float* __restrict__ x,
                         const float* __restrict__ bw,
                         const float* __restrict__ sw) {
    int blk = blockIdx.x;
    if (blk < NA_BLOCKS) {
        // build A[b, 6I] fp16 — 2 consecutive i per thread; streaming stores
        size_t idx = (size_t)blk * 256 + threadIdx.x;
        size_t b = idx / (I_DIM / 2);
        size_t i = (idx % (I_DIM / 2)) * 2;
        float2 v = *reinterpret_cast<const float2*>(x + b * I_DIM + i);
        __half* row = g_A + b * K_DIM;
        float s0 = v.x / (1.0f + __expf(-v.x));
        float s1 = v.y / (1.0f + __expf(-v.y));
        __half2 h = __floats2half2_rn(s0, s1);
        st_stream32(row + i, *reinterpret_cast<uint32_t*>(&h));
#pragma unroll
        for (int g = 0; g < 5; ++g) {
            float gc = -1.0f + 0.5f * (float)g;
            float d0 = v.x - gc, d1 = v.y - gc;
            __half2 hb = __floats2half2_rn(__expf(-5.0f * d0 * d0), __expf(-5.0f * d1 * d1));
            st_stream32(row + (size_t)(g + 1) * I_DIM + i, *reinterpret_cast<uint32_t*>(&hb));
        }
    } else {
        // build Wc[o, 6I] fp16 (hot data — normal stores, stays in L2)
        size_t idx = (size_t)(blk - NA_BLOCKS) * 256 + threadIdx.x;
        size_t o = idx >> 11;
        size_t i = idx & 2047;
        __half* row = g_W + o * K_DIM;
        row[i] = __float2half(bw[idx]);
        const float* sp = sw + idx * 5;
#pragma unroll
        for (int g = 0; g < 5; ++g)
            row[(size_t)(g + 1) * I_DIM + i] = __float2half(sp[g]);
    }
}

// ---------------- pass 2: persistent pipelined HMMA GEMM  out[B,O] = A @ Wc^T ----------------
// 128 threads (4 warps, 64x64 warptile), 2 CTAs/SM, persistent over ~7 tiles.
// Prefetch cp.async spread across sub-iterations; the last two kt's prefetch
// slots load the NEXT tile's stages 0/1 so the per-tile prologue is fully
// pipelined (only the first tile pays prologue latency).
__global__ void __launch_bounds__(128, 2)
gemm_kernel(float* __restrict__ out) {
    extern __shared__ __align__(1024) char smem[];
    uint32_t sb = smem_u32(smem);
    int tid = threadIdx.x;
    int wid = tid >> 5, lid = tid & 31;
    int mw = wid >> 1;   // 0..1 -> M offset mw*64
    int nw = wid & 1;    // 0..1 -> N offset nw*64
    int sub_xor = (wid & 1) << 1;   // warps 1,3 do subs in order 2,3,0,1

    // per-thread ldmatrix row/col components (constant across tiles)
    int a_row = mw * 64 + (lid & 15);                       // + mt*16
    int a_colb_base = (lid >> 4) * 16;                      // + sub*32
    int b_row = nw * 64 + ((lid >> 4) << 3) + (lid & 7);    // + nt*16
    int b_colb_base = ((lid >> 3) & 1) * 16;                // + sub*32
    int qr = lid >> 2, qc = (lid & 3) * 2;

    // per-thread cp.async source/dest components
    // full stage: j=0..7  ->  v = tid + 128*j ; r = v>>3 ; c = v&7
    // quarter q covers j = 2q, 2q+1

    // ---- full-stage loader (first-tile prologue only)
    auto load_stage_full = [&](int s, const __half* gA, const __half* gB) {
        uint32_t sA = sb + s * STAGE_BYTES;
        uint32_t sBp = sA + A_STAGE_BYTES;
#pragma unroll
        for (int j = 0; j < 8; ++j) {
            int v = tid + 128 * j;
            int r = v >> 3, c = v & 7;
            cp_async16(sA + SWZ(r * 128 + c * 16), gA + (size_t)r * K_DIM + c * 8);
        }
#pragma unroll
        for (int j = 0; j < 8; ++j) {
            int v = tid + 128 * j;
            int r = v >> 3, c = v & 7;
            cp_async16(sBp + SWZ(r * 128 + c * 16), gB + (size_t)r * K_DIM + c * 8);
        }
    };

    // ---- quarter-stage loader
    auto load_stage_part = [&](int s, const __half* gA, const __half* gB, int q) {
        uint32_t sA = sb + s * STAGE_BYTES;
        uint32_t sBp = sA + A_STAGE_BYTES;
#pragma unroll
        for (int jj = 0; jj < 2; ++jj) {
            int v = tid + 128 * (q * 2 + jj);
            int r = v >> 3, c = v & 7;
            cp_async16(sA + SWZ(r * 128 + c * 16), gA + (size_t)r * K_DIM + c * 8);
        }
#pragma unroll
        for (int jj = 0; jj < 2; ++jj) {
            int v = tid + 128 * (q * 2 + jj);
            int r = v >> 3, c = v & 7;
            cp_async16(sBp + SWZ(r * 128 + c * 16), gB + (size_t)r * K_DIM + c * 8);
        }
    };

    // ---- first-tile prologue: stages 0..1
    {
        int t0 = blockIdx.x;
        int m0 = (t0 >> 4) * MT, n0 = (t0 & 15) * NT;
#pragma unroll
        for (int s = 0; s < STAGES - 1; ++s) {
            load_stage_full(s, g_A + (size_t)m0 * K_DIM + (size_t)s * KC,
                               g_W + (size_t)n0 * K_DIM + (size_t)s * KC);
            cp_commit();
        }
    }

#pragma unroll 1
    for (int tile = blockIdx.x; tile < NTILES; tile += PERSIST_CTAS) {
        int m0 = (tile >> 4) * MT;          // N-fastest order for A L2 reuse
        int n0 = (tile & 15) * NT;
        int ntile = tile + PERSIST_CTAS;
        bool has_next = ntile < NTILES;
        int nm0 = has_next ? (ntile >> 4) * MT : m0;
        int nn0 = has_next ? (ntile & 15) * NT : n0;

        float acc[4][8][4];
#pragma unroll
        for (int a = 0; a < 4; ++a)
#pragma unroll
            for (int b = 0; b < 8; ++b)
#pragma unroll
                for (int c = 0; c < 4; ++c) acc[a][b][c] = 0.0f;

        int stage = 0;
#pragma unroll 1
        for (int kt = 0; kt < KITERS; ++kt) {
            cp_wait1();
            __syncthreads();

            uint32_t sA = sb + stage * STAGE_BYTES;
            uint32_t sBp = sA + A_STAGE_BYTES;

            int pf = stage + 2;
            if (pf >= STAGES) pf -= STAGES;

            // prefetch target: current tile kt+2, or next tile's kt-(KITERS-2)
            const __half *pA, *pB;
            bool do_pf;
            if (kt < KITERS - 2) {
                pA = g_A + (size_t)m0 * K_DIM + (size_t)(kt + 2) * KC;
                pB = g_W + (size_t)n0 * K_DIM + (size_t)(kt + 2) * KC;
                do_pf = true;
            } else {
                // kt = 190 -> next kt'=0 into stage 0; kt = 191 -> kt'=1 into stage 1
                int nk = kt - (KITERS - 2);
                pA = g_A + (size_t)nm0 * K_DIM + (size_t)nk * KC;
                pB = g_W + (size_t)nn0 * K_DIM + (size_t)nk * KC;
                do_pf = has_next;
            }

#pragma unroll
            for (int subi = 0; subi < 4; ++subi) {
                int sub = subi ^ sub_xor;   // odd warps rotate sub order
                uint32_t aF[4][4], bF[4][4];
                int acolb = a_colb_base + sub * 32;
                int bcolb = b_colb_base + sub * 32;
#pragma unroll
                for (int mt = 0; mt < 4; ++mt)
                    ldmatrix_x4(aF[mt], sA + SWZ((a_row + mt * 16) * 128 + acolb));
#pragma unroll
                for (int nt = 0; nt < 4; ++nt)
                    ldmatrix_x4(bF[nt], sBp + SWZ((b_row + nt * 16) * 128 + bcolb));

                // spread prefetch: 4 cp.async per thread per sub
                if (do_pf) load_stage_part(pf, pA, pB, subi);

#pragma unroll
                for (int mt = 0; mt < 4; ++mt)
#pragma unroll
                    for (int n8 = 0; n8 < 8; ++n8)
                        mma16816(acc[mt][n8], aF[mt], bF[n8 >> 1] + (n8 & 1) * 2);
            }
            cp_commit();   // one group per kt (possibly empty) keeps wait_group invariant
            ++stage;
            if (stage == STAGES) stage = 0;
        }

        // ---- epilogue (overlaps the in-flight next-tile prologue copies)
#pragma unroll
        for (int mt = 0; mt < 4; ++mt) {
#pragma unroll
            for (int n8 = 0; n8 < 8; ++n8) {
                int row = m0 + mw * 64 + mt * 16 + qr;
                int col = n0 + nw * 64 + n8 * 8 + qc;
                float2* p0 = reinterpret_cast<float2*>(out + (size_t)row * O_DIM + col);
                *p0 = make_float2(acc[mt][n8][0], acc[mt][n8][1]);
                float2* p1 = reinterpret_cast<float2*>(out + (size_t)(row + 8) * O_DIM + col);
                *p1 = make_float2(acc[mt][n8][2], acc[mt][n8][3]);
            }
        }
    }
}

// ---------------- launch ----------------
extern "C" void kernel_launch(void* const* d_in, const int* in_sizes, int n_in,
                              void* d_out, int out_size) {
    const float* x  = (const float*)d_in[0];
    const float* bw = (const float*)d_in[1];
    const float* sw = (const float*)d_in[2];
    float* out = (float*)d_out;

    build_AW<<<NA_BLOCKS + NW_BLOCKS, 256>>>(x, bw, sw);

    cudaFuncSetAttribute(gemm_kernel, cudaFuncAttributeMaxDynamicSharedMemorySize, SMEM_BYTES);
    gemm_kernel<<<PERSIST_CTAS, 128, SMEM_BYTES>>>(out);
}

// round 12
// speedup vs baseline: 1.0265x; 1.0265x over previous
#include <cuda_runtime.h>
#include <cuda_fp16.h>
#include <cstdint>

// ---------------- problem constants ----------------
#define B_DIM 16384
#define I_DIM 2048
#define O_DIM 2048
#define K_DIM 12288              // 6 * I_DIM (silu panel + 5 RBF panels)
#define KC 64                    // K elems per pipeline stage (64 fp16 = 128 B row)
#define MT 128                   // CTA tile M
#define NT 128                   // CTA tile N
#define STAGES 3
#define KITERS (K_DIM / KC)      // 192

#define A_STAGE_BYTES (MT * 128)                     // 16384
#define B_STAGE_BYTES (NT * 128)                     // 16384
#define STAGE_BYTES (A_STAGE_BYTES + B_STAGE_BYTES)  // 32768
#define SMEM_BYTES (STAGES * STAGE_BYTES)            // 98304 (x2 CTAs = 192KB/SM)

#define NTILES_X (O_DIM / NT)    // 16
#define NTILES (B_DIM / MT * NTILES_X)   // 2048
#define PERSIST_CTAS 296         // 2 per SM x 148 SMs

// ---------------- scratch (device globals; no runtime allocation) ----------------
__device__ __align__(1024) __half g_A[(size_t)B_DIM * K_DIM];   // ~403 MB
__device__ __align__(1024) __half g_W[(size_t)O_DIM * K_DIM];   // ~50 MB

// ---------------- helpers (compute_103-safe PTX only) ----------------
__device__ __forceinline__ uint32_t smem_u32(const void* p) {
    return (uint32_t)__cvta_generic_to_shared(p);
}

// XOR swizzle: 128B rows, 16B granularity, conflict-free ldmatrix + cp.async
#define SWZ(o) ((o) ^ (((o) >> 3) & 0x70))

__device__ __forceinline__ void cp_async16(uint32_t saddr, const void* gptr) {
    asm volatile("cp.async.cg.shared.global [%0], [%1], 16;"
                 :: "r"(saddr), "l"(gptr) : "memory");
}
__device__ __forceinline__ void cp_commit() {
    asm volatile("cp.async.commit_group;" ::: "memory");
}
__device__ __forceinline__ void cp_wait1() {
    asm volatile("cp.async.wait_group 1;" ::: "memory");
}

__device__ __forceinline__ void st_stream32(void* gptr, uint32_t v) {
    asm volatile("st.global.cs.b32 [%0], %1;" :: "l"(gptr), "r"(v) : "memory");
}
__device__ __forceinline__ void st_stream_f2(void* gptr, float a, float b) {
    asm volatile("st.global.cs.v2.f32 [%0], {%1, %2};" :: "l"(gptr), "f"(a), "f"(b) : "memory");
}

__device__ __forceinline__ void ldmatrix_x4(uint32_t* r, uint32_t addr) {
    asm volatile("ldmatrix.sync.aligned.m8n8.x4.shared.b16 {%0,%1,%2,%3}, [%4];"
                 : "=r"(r[0]), "=r"(r[1]), "=r"(r[2]), "=r"(r[3]) : "r"(addr));
}

__device__ __forceinline__ void mma16816(float* c, const uint32_t* a, const uint32_t* b) {
    asm volatile(
        "mma.sync.aligned.m16n8k16.row.col.f32.f16.f16.f32 "
        "{%0,%1,%2,%3}, {%4,%5,%6,%7}, {%8,%9}, {%0,%1,%2,%3};"
        : "+f"(c[0]), "+f"(c[1]), "+f"(c[2]), "+f"(c[3])
        : "r"(a[0]), "r"(a[1]), "r"(a[2]), "r"(a[3]), "r"(b[0]), "r"(b[1]));
}

// ---------------- pass 1 (merged): expanded activation + combined weight ----------------
#define NA_BLOCKS (B_DIM * I_DIM / 2 / 256)   // 65536
#define NW_BLOCKS (O_DIM * I_DIM / 256)       // 16384

__global__ void build_AW(const float* __restrict__ x,
                         const float* __restrict__ bw,
                         const float* __restrict__ sw) {
    int blk = blockIdx.x;
    if (blk < NA_BLOCKS) {
        // build A[b, 6I] fp16 — 2 consecutive i per thread; streaming stores
        size_t idx = (size_t)blk * 256 + threadIdx.x;
        size_t b = idx / (I_DIM / 2);
        size_t i = (idx % (I_DIM / 2)) * 2;
        float2 v = *reinterpret_cast<const float2*>(x + b * I_DIM + i);
        __half* row = g_A + b * K_DIM;
        float s0 = v.x / (1.0f + __expf(-v.x));
        float s1 = v.y / (1.0f + __expf(-v.y));
        __half2 h = __floats2half2_rn(s0, s1);
        st_stream32(row + i, *reinterpret_cast<uint32_t*>(&h));
#pragma unroll
        for (int g = 0; g < 5; ++g) {
            float gc = -1.0f + 0.5f * (float)g;
            float d0 = v.x - gc, d1 = v.y - gc;
            __half2 hb = __floats2half2_rn(__expf(-5.0f * d0 * d0), __expf(-5.0f * d1 * d1));
            st_stream32(row + (size_t)(g + 1) * I_DIM + i, *reinterpret_cast<uint32_t*>(&hb));
        }
    } else {
        // build Wc[o, 6I] fp16 (hot data — normal stores, stays in L2)
        size_t idx = (size_t)(blk - NA_BLOCKS) * 256 + threadIdx.x;
        size_t o = idx >> 11;
        size_t i = idx & 2047;
        __half* row = g_W + o * K_DIM;
        row[i] = __float2half(bw[idx]);
        const float* sp = sw + idx * 5;
#pragma unroll
        for (int g = 0; g < 5; ++g)
            row[(size_t)(g + 1) * I_DIM + i] = __float2half(sp[g]);
    }
}

// ---------------- pass 2: persistent pipelined HMMA GEMM  out[B,O] = A @ Wc^T ----------------
// 128 threads (4 warps, 64x64 warptile), 2 CTAs/SM, persistent over ~7 tiles.
// Mainloop identical to the best measured config (R10). Epilogue uses
// evict-first stores so out-writes don't pollute L2 A/B residency.
__global__ void __launch_bounds__(128, 2)
gemm_kernel(float* __restrict__ out) {
    extern __shared__ __align__(1024) char smem[];
    uint32_t sb = smem_u32(smem);
    int tid = threadIdx.x;
    int wid = tid >> 5, lid = tid & 31;
    int mw = wid >> 1;   // 0..1 -> M offset mw*64
    int nw = wid & 1;    // 0..1 -> N offset nw*64
    int sub_xor = (wid & 1) << 1;   // warps 1,3 do subs in order 2,3,0,1

    // per-thread ldmatrix row/col components (constant across tiles)
    int a_row = mw * 64 + (lid & 15);                       // + mt*16
    int a_colb_base = (lid >> 4) * 16;                      // + sub*32
    int b_row = nw * 64 + ((lid >> 4) << 3) + (lid & 7);    // + nt*16
    int b_colb_base = ((lid >> 3) & 1) * 16;                // + sub*32
    int qr = lid >> 2, qc = (lid & 3) * 2;

#pragma unroll 1
    for (int tile = blockIdx.x; tile < NTILES; tile += PERSIST_CTAS) {
        int m0 = (tile >> 4) * MT;          // tile/16 — N-fastest order for A L2 reuse
        int n0 = (tile & 15) * NT;

        float acc[4][8][4];
#pragma unroll
        for (int a = 0; a < 4; ++a)
#pragma unroll
            for (int b = 0; b < 8; ++b)
#pragma unroll
                for (int c = 0; c < 4; ++c) acc[a][b][c] = 0.0f;

        // ---- full-stage loader (prologue only)
        auto load_stage = [&](int s, int kt) {
            const __half* gA = g_A + (size_t)m0 * K_DIM + (size_t)kt * KC;
            const __half* gB = g_W + (size_t)n0 * K_DIM + (size_t)kt * KC;
            uint32_t sA = sb + s * STAGE_BYTES;
            uint32_t sBp = sA + A_STAGE_BYTES;
#pragma unroll
            for (int j = 0; j < 8; ++j) {
                int v = tid + 128 * j;
                int r = v >> 3, c = v & 7;
                cp_async16(sA + SWZ(r * 128 + c * 16), gA + (size_t)r * K_DIM + c * 8);
            }
#pragma unroll
            for (int j = 0; j < 8; ++j) {
                int v = tid + 128 * j;
                int r = v >> 3, c = v & 7;
                cp_async16(sBp + SWZ(r * 128 + c * 16), gB + (size_t)r * K_DIM + c * 8);
            }
        };

        // ---- quarter-stage loader: issues j = 2*q, 2*q+1 for both A and B
        auto load_stage_part = [&](int s, int kt, int q) {
            const __half* gA = g_A + (size_t)m0 * K_DIM + (size_t)kt * KC;
            const __half* gB = g_W + (size_t)n0 * K_DIM + (size_t)kt * KC;
            uint32_t sA = sb + s * STAGE_BYTES;
            uint32_t sBp = sA + A_STAGE_BYTES;
#pragma unroll
            for (int jj = 0; jj < 2; ++jj) {
                int v = tid + 128 * (q * 2 + jj);
                int r = v >> 3, c = v & 7;
                cp_async16(sA + SWZ(r * 128 + c * 16), gA + (size_t)r * K_DIM + c * 8);
            }
#pragma unroll
            for (int jj = 0; jj < 2; ++jj) {
                int v = tid + 128 * (q * 2 + jj);
                int r = v >> 3, c = v & 7;
                cp_async16(sBp + SWZ(r * 128 + c * 16), gB + (size_t)r * K_DIM + c * 8);
            }
        };

        // ---- prologue: stages 0..1  (safe vs previous tile: its last kt used stage 2)
#pragma unroll
        for (int s = 0; s < STAGES - 1; ++s) {
            load_stage(s, s);
            cp_commit();
        }

        int stage = 0;
#pragma unroll 1
        for (int kt = 0; kt < KITERS; ++kt) {
            cp_wait1();
            __syncthreads();

            uint32_t sA = sb + stage * STAGE_BYTES;
            uint32_t sBp = sA + A_STAGE_BYTES;

            int pf = stage + 2;
            if (pf >= STAGES) pf -= STAGES;
            bool do_pf = (kt + STAGES - 1 < KITERS);

#pragma unroll
            for (int subi = 0; subi < 4; ++subi) {
                int sub = subi ^ sub_xor;   // odd warps: 2,3,0,1 — decorrelate ldsm bursts
                uint32_t aF[4][4], bF[4][4];
                int acolb = a_colb_base + sub * 32;
                int bcolb = b_colb_base + sub * 32;
#pragma unroll
                for (int mt = 0; mt < 4; ++mt)
                    ldmatrix_x4(aF[mt], sA + SWZ((a_row + mt * 16) * 128 + acolb));
#pragma unroll
                for (int nt = 0; nt < 4; ++nt)
                    ldmatrix_x4(bF[nt], sBp + SWZ((b_row + nt * 16) * 128 + bcolb));

                // spread the next-stage prefetch: 4 cp.async per thread per sub
                if (do_pf) load_stage_part(pf, kt + STAGES - 1, subi);

#pragma unroll
                for (int mt = 0; mt < 4; ++mt)
#pragma unroll
                    for (int n8 = 0; n8 < 8; ++n8)
                        mma16816(acc[mt][n8], aF[mt], bF[n8 >> 1] + (n8 & 1) * 2);
            }
            cp_commit();   // one group per kt (empty at tail) keeps wait_group invariant
            ++stage;
            if (stage == STAGES) stage = 0;
        }

        // ---- epilogue: evict-first stores (out is write-once, never re-read here)
#pragma unroll
        for (int mt = 0; mt < 4; ++mt) {
#pragma unroll
            for (int n8 = 0; n8 < 8; ++n8) {
                int row = m0 + mw * 64 + mt * 16 + qr;
                int col = n0 + nw * 64 + n8 * 8 + qc;
                st_stream_f2(out + (size_t)row * O_DIM + col,
                             acc[mt][n8][0], acc[mt][n8][1]);
                st_stream_f2(out + (size_t)(row + 8) * O_DIM + col,
                             acc[mt][n8][2], acc[mt][n8][3]);
            }
        }
    }
}

// ---------------- launch ----------------
extern "C" void kernel_launch(void* const* d_in, const int* in_sizes, int n_in,
                              void* d_out, int out_size) {
    const float* x  = (const float*)d_in[0];
    const float* bw = (const float*)d_in[1];
    const float* sw = (const float*)d_in[2];
    float* out = (float*)d_out;

    build_AW<<<NA_BLOCKS + NW_BLOCKS, 256>>>(x, bw, sw);

    cudaFuncSetAttribute(gemm_kernel, cudaFuncAttributeMaxDynamicSharedMemorySize, SMEM_BYTES);
    gemm_kernel<<<PERSIST_CTAS, 128, SMEM_BYTES>>>(out);
}

// round 13
// speedup vs baseline: 1.0362x; 1.0095x over previous
#include <cuda_runtime.h>
#include <cuda_fp16.h>
#include <cstdint>

// ---------------- problem constants ----------------
#define B_DIM 16384
#define I_DIM 2048
#define O_DIM 2048
#define K_DIM 12288              // 6 * I_DIM (silu panel + 5 RBF panels)
#define KC 64                    // K elems per pipeline stage (64 fp16 = 128 B row)
#define MT 128                   // CTA tile M
#define NT 128                   // CTA tile N
#define STAGES 3
#define KITERS (K_DIM / KC)      // 192

#define A_STAGE_BYTES (MT * 128)                     // 16384
#define B_STAGE_BYTES (NT * 128)                     // 16384
#define STAGE_BYTES (A_STAGE_BYTES + B_STAGE_BYTES)  // 32768
#define SMEM_BYTES (STAGES * STAGE_BYTES)            // 98304 (x2 CTAs = 192KB/SM)

#define NTILES_X (O_DIM / NT)    // 16
#define NTILES (B_DIM / MT * NTILES_X)   // 2048
#define PERSIST_CTAS 296         // 2 per SM x 148 SMs

// ---------------- scratch (device globals; no runtime allocation) ----------------
__device__ __align__(1024) __half g_A[(size_t)B_DIM * K_DIM];   // ~403 MB
__device__ __align__(1024) __half g_W[(size_t)O_DIM * K_DIM];   // ~50 MB

// ---------------- helpers (compute_103-safe PTX only) ----------------
__device__ __forceinline__ uint32_t smem_u32(const void* p) {
    return (uint32_t)__cvta_generic_to_shared(p);
}

// XOR swizzle: 128B rows, 16B granularity, conflict-free ldmatrix + cp.async
#define SWZ(o) ((o) ^ (((o) >> 3) & 0x70))

__device__ __forceinline__ void cp_async16(uint32_t saddr, const void* gptr) {
    asm volatile("cp.async.cg.shared.global [%0], [%1], 16;"
                 :: "r"(saddr), "l"(gptr) : "memory");
}
__device__ __forceinline__ void cp_commit() {
    asm volatile("cp.async.commit_group;" ::: "memory");
}
__device__ __forceinline__ void cp_wait1() {
    asm volatile("cp.async.wait_group 1;" ::: "memory");
}

__device__ __forceinline__ void ldmatrix_x4(uint32_t* r, uint32_t addr) {
    asm volatile("ldmatrix.sync.aligned.m8n8.x4.shared.b16 {%0,%1,%2,%3}, [%4];"
                 : "=r"(r[0]), "=r"(r[1]), "=r"(r[2]), "=r"(r[3]) : "r"(addr));
}

__device__ __forceinline__ void mma16816(float* c, const uint32_t* a, const uint32_t* b) {
    asm volatile(
        "mma.sync.aligned.m16n8k16.row.col.f32.f16.f16.f32 "
        "{%0,%1,%2,%3}, {%4,%5,%6,%7}, {%8,%9}, {%0,%1,%2,%3};"
        : "+f"(c[0]), "+f"(c[1]), "+f"(c[2]), "+f"(c[3])
        : "r"(a[0]), "r"(a[1]), "r"(a[2]), "r"(a[3]), "r"(b[0]), "r"(b[1]));
}

// ---------------- pass 1 (merged): expanded activation + combined weight ----------------
// build_A: 4 consecutive i per thread -> float4 load, 64-bit stores per panel.
#define NA_BLOCKS (B_DIM * I_DIM / 4 / 256)   // 32768
#define NW_BLOCKS (O_DIM * I_DIM / 256)       // 16384

__global__ void build_AW(const float* __restrict__ x,
                         const float* __restrict__ bw,
                         const float* __restrict__ sw) {
    int blk = blockIdx.x;
    if (blk < NA_BLOCKS) {
        size_t idx = (size_t)blk * 256 + threadIdx.x;   // over B*I/4
        size_t b = idx / (I_DIM / 4);
        size_t i = (idx % (I_DIM / 4)) * 4;
        float4 v = *reinterpret_cast<const float4*>(x + b * I_DIM + i);
        __half* row = g_A + b * K_DIM;

        // silu panel
        float s0 = v.x / (1.0f + __expf(-v.x));
        float s1 = v.y / (1.0f + __expf(-v.y));
        float s2 = v.z / (1.0f + __expf(-v.z));
        float s3 = v.w / (1.0f + __expf(-v.w));
        __half2 p0 = __floats2half2_rn(s0, s1);
        __half2 p1 = __floats2half2_rn(s2, s3);
        uint2 pk;
        pk.x = *reinterpret_cast<uint32_t*>(&p0);
        pk.y = *reinterpret_cast<uint32_t*>(&p1);
        *reinterpret_cast<uint2*>(row + i) = pk;

        // 5 RBF panels
#pragma unroll
        for (int g = 0; g < 5; ++g) {
            float gc = -1.0f + 0.5f * (float)g;
            float d0 = v.x - gc, d1 = v.y - gc, d2 = v.z - gc, d3 = v.w - gc;
            __half2 q0 = __floats2half2_rn(__expf(-5.0f * d0 * d0), __expf(-5.0f * d1 * d1));
            __half2 q1 = __floats2half2_rn(__expf(-5.0f * d2 * d2), __expf(-5.0f * d3 * d3));
            uint2 qk;
            qk.x = *reinterpret_cast<uint32_t*>(&q0);
            qk.y = *reinterpret_cast<uint32_t*>(&q1);
            *reinterpret_cast<uint2*>(row + (size_t)(g + 1) * I_DIM + i) = qk;
        }
    } else {
        // build Wc[o, 6I] fp16
        size_t idx = (size_t)(blk - NA_BLOCKS) * 256 + threadIdx.x;
        size_t o = idx >> 11;
        size_t i = idx & 2047;
        __half* row = g_W + o * K_DIM;
        row[i] = __float2half(bw[idx]);
        const float* sp = sw + idx * 5;
#pragma unroll
        for (int g = 0; g < 5; ++g)
            row[(size_t)(g + 1) * I_DIM + i] = __float2half(sp[g]);
    }
}

// ---------------- pass 2: persistent pipelined HMMA GEMM  out[B,O] = A @ Wc^T ----------------
// 128 threads (4 warps, 64x64 warptile), 2 CTAs/SM, persistent over ~7 tiles.
// Best measured mainloop (R10): spread prefetch + rotated sub order.
__global__ void __launch_bounds__(128, 2)
gemm_kernel(float* __restrict__ out) {
    extern __shared__ __align__(1024) char smem[];
    uint32_t sb = smem_u32(smem);
    int tid = threadIdx.x;
    int wid = tid >> 5, lid = tid & 31;
    int mw = wid >> 1;   // 0..1 -> M offset mw*64
    int nw = wid & 1;    // 0..1 -> N offset nw*64
    int sub_xor = (wid & 1) << 1;   // warps 1,3 do subs in order 2,3,0,1

    // per-thread ldmatrix row/col components (constant across tiles)
    int a_row = mw * 64 + (lid & 15);                       // + mt*16
    int a_colb_base = (lid >> 4) * 16;                      // + sub*32
    int b_row = nw * 64 + ((lid >> 4) << 3) + (lid & 7);    // + nt*16
    int b_colb_base = ((lid >> 3) & 1) * 16;                // + sub*32
    int qr = lid >> 2, qc = (lid & 3) * 2;

#pragma unroll 1
    for (int tile = blockIdx.x; tile < NTILES; tile += PERSIST_CTAS) {
        int m0 = (tile >> 4) * MT;          // tile/16 — N-fastest order for A L2 reuse
        int n0 = (tile & 15) * NT;

        float acc[4][8][4];
#pragma unroll
        for (int a = 0; a < 4; ++a)
#pragma unroll
            for (int b = 0; b < 8; ++b)
#pragma unroll
                for (int c = 0; c < 4; ++c) acc[a][b][c] = 0.0f;

        // ---- full-stage loader (prologue only)
        auto load_stage = [&](int s, int kt) {
            const __half* gA = g_A + (size_t)m0 * K_DIM + (size_t)kt * KC;
            const __half* gB = g_W + (size_t)n0 * K_DIM + (size_t)kt * KC;
            uint32_t sA = sb + s * STAGE_BYTES;
            uint32_t sBp = sA + A_STAGE_BYTES;
#pragma unroll
            for (int j = 0; j < 8; ++j) {
                int v = tid + 128 * j;
                int r = v >> 3, c = v & 7;
                cp_async16(sA + SWZ(r * 128 + c * 16), gA + (size_t)r * K_DIM + c * 8);
            }
#pragma unroll
            for (int j = 0; j < 8; ++j) {
                int v = tid + 128 * j;
                int r = v >> 3, c = v & 7;
                cp_async16(sBp + SWZ(r * 128 + c * 16), gB + (size_t)r * K_DIM + c * 8);
            }
        };

        // ---- quarter-stage loader: issues j = 2*q, 2*q+1 for both A and B
        auto load_stage_part = [&](int s, int kt, int q) {
            const __half* gA = g_A + (size_t)m0 * K_DIM + (size_t)kt * KC;
            const __half* gB = g_W + (size_t)n0 * K_DIM + (size_t)kt * KC;
            uint32_t sA = sb + s * STAGE_BYTES;
            uint32_t sBp = sA + A_STAGE_BYTES;
#pragma unroll
            for (int jj = 0; jj < 2; ++jj) {
                int v = tid + 128 * (q * 2 + jj);
                int r = v >> 3, c = v & 7;
                cp_async16(sA + SWZ(r * 128 + c * 16), gA + (size_t)r * K_DIM + c * 8);
            }
#pragma unroll
            for (int jj = 0; jj < 2; ++jj) {
                int v = tid + 128 * (q * 2 + jj);
                int r = v >> 3, c = v & 7;
                cp_async16(sBp + SWZ(r * 128 + c * 16), gB + (size_t)r * K_DIM + c * 8);
            }
        };

        // ---- prologue: stages 0..1  (safe vs previous tile: its last kt used stage 2)
#pragma unroll
        for (int s = 0; s < STAGES - 1; ++s) {
            load_stage(s, s);
            cp_commit();
        }

        int stage = 0;
#pragma unroll 1
        for (int kt = 0; kt < KITERS; ++kt) {
            cp_wait1();
            __syncthreads();

            uint32_t sA = sb + stage * STAGE_BYTES;
            uint32_t sBp = sA + A_STAGE_BYTES;

            int pf = stage + 2;
            if (pf >= STAGES) pf -= STAGES;
            bool do_pf = (kt + STAGES - 1 < KITERS);

#pragma unroll
            for (int subi = 0; subi < 4; ++subi) {
                int sub = subi ^ sub_xor;   // odd warps: 2,3,0,1 — decorrelate ldsm bursts
                uint32_t aF[4][4], bF[4][4];
                int acolb = a_colb_base + sub * 32;
                int bcolb = b_colb_base + sub * 32;
#pragma unroll
                for (int mt = 0; mt < 4; ++mt)
                    ldmatrix_x4(aF[mt], sA + SWZ((a_row + mt * 16) * 128 + acolb));
#pragma unroll
                for (int nt = 0; nt < 4; ++nt)
                    ldmatrix_x4(bF[nt], sBp + SWZ((b_row + nt * 16) * 128 + bcolb));

                // spread the next-stage prefetch: 4 cp.async per thread per sub
                if (do_pf) load_stage_part(pf, kt + STAGES - 1, subi);

#pragma unroll
                for (int mt = 0; mt < 4; ++mt)
#pragma unroll
                    for (int n8 = 0; n8 < 8; ++n8)
                        mma16816(acc[mt][n8], aF[mt], bF[n8 >> 1] + (n8 & 1) * 2);
            }
            cp_commit();   // one group per kt (empty at tail) keeps wait_group invariant
            ++stage;
            if (stage == STAGES) stage = 0;
        }

        // ---- epilogue: D frag layout c0:(r,c) c1:(r,c+1) c2:(r+8,c) c3:(r+8,c+1)
#pragma unroll
        for (int mt = 0; mt < 4; ++mt) {
#pragma unroll
            for (int n8 = 0; n8 < 8; ++n8) {
                int row = m0 + mw * 64 + mt * 16 + qr;
                int col = n0 + nw * 64 + n8 * 8 + qc;
                float2* p0 = reinterpret_cast<float2*>(out + (size_t)row * O_DIM + col);
                *p0 = make_float2(acc[mt][n8][0], acc[mt][n8][1]);
                float2* p1 = reinterpret_cast<float2*>(out + (size_t)(row + 8) * O_DIM + col);
                *p1 = make_float2(acc[mt][n8][2], acc[mt][n8][3]);
            }
        }
    }
}

// ---------------- launch ----------------
extern "C" void kernel_launch(void* const* d_in, const int* in_sizes, int n_in,
                              void* d_out, int out_size) {
    const float* x  = (const float*)d_in[0];
    const float* bw = (const float*)d_in[1];
    const float* sw = (const float*)d_in[2];
    float* out = (float*)d_out;

    build_AW<<<NA_BLOCKS + NW_BLOCKS, 256>>>(x, bw, sw);

    cudaFuncSetAttribute(gemm_kernel, cudaFuncAttributeMaxDynamicSharedMemorySize, SMEM_BYTES);
    gemm_kernel<<<PERSIST_CTAS, 128, SMEM_BYTES>>>(out);
}